// round 3
// baseline (speedup 1.0000x reference)
#include <cuda_runtime.h>
#include <math.h>

#define S_LEN  1024
#define HDIM   1024
#define NTOK   4096            // B*S
#define NHEADS 16
#define DHEAD  64
#define PATHS  16

// ---------------- scratch (static __device__, no allocation) ----------------
__device__ float4 g_x_   [NTOK*HDIM/4];        // ln1 out
__device__ float4 g_qkv_ [NTOK*3*HDIM/4];      // qkv
__device__ float4 g_ctx_ [NTOK*HDIM/4];        // attention context
__device__ float4 g_h_   [NTOK*HDIM/4];        // residual-1 out
__device__ float4 g_x2_  [NTOK*HDIM/4];        // ln2 out
__device__ float4 g_r1_  [NTOK*256/4];         // router hidden
__device__ float4 g_w_   [NTOK*PATHS/4];       // pathway weights
__device__ float4 g_int_ [(long long)PATHS*NTOK*256/4]; // pathway intermediates

// ---------------- LayerNorm (one block per row of 1024) ----------------
__global__ __launch_bounds__(256) void ln_kernel(
    const float* __restrict__ x, const float* __restrict__ gamma,
    const float* __restrict__ beta, float* __restrict__ y)
{
    long long row = blockIdx.x;
    const float* xr = x + row * HDIM;
    float* yr = y + row * HDIM;
    int tid = threadIdx.x;

    float4 v = *(const float4*)&xr[tid * 4];
    float s  = v.x + v.y + v.z + v.w;
    float ss = v.x*v.x + v.y*v.y + v.z*v.z + v.w*v.w;
    #pragma unroll
    for (int o = 16; o; o >>= 1) {
        s  += __shfl_xor_sync(0xffffffffu, s,  o);
        ss += __shfl_xor_sync(0xffffffffu, ss, o);
    }
    __shared__ float rs[8], rss[8];
    int w = tid >> 5, ln = tid & 31;
    if (ln == 0) { rs[w] = s; rss[w] = ss; }
    __syncthreads();
    s = 0.f; ss = 0.f;
    #pragma unroll
    for (int i = 0; i < 8; i++) { s += rs[i]; ss += rss[i]; }

    float mean = s * (1.0f / HDIM);
    float var  = ss * (1.0f / HDIM) - mean * mean;
    float inv  = rsqrtf(var + 1e-5f);

    float4 g = *(const float4*)&gamma[tid * 4];
    float4 b = *(const float4*)&beta[tid * 4];
    float4 o;
    o.x = (v.x - mean) * inv * g.x + b.x;
    o.y = (v.y - mean) * inv * g.y + b.y;
    o.z = (v.z - mean) * inv * g.z + b.z;
    o.w = (v.w - mean) * inv * g.w + b.w;
    *(float4*)&yr[tid * 4] = o;
}

// ---------------- generic SGEMM: C[M,N] = A[M,K] @ B[N,K]^T + epilogue ------
// BM=128, BN=64, BK=16, 256 threads, 8x4 microtile.
// EPI: 0=bias  1=bias+res  2=bias+relu  3=gelu(bias)  4=res + (acc+bias)*w[row,z]
__device__ __forceinline__ float gelu_tanh(float x) {
    float t = tanhf(0.7978845608028654f * (x + 0.044715f * x * x * x));
    return 0.5f * x * (1.0f + t);
}

template<int EPI>
__global__ __launch_bounds__(256) void sgemm_kernel(
    const float* __restrict__ A, int lda, long long aZ,
    const float* __restrict__ B, int ldb, long long bZ,
    float* __restrict__ C, int ldc, long long cZ,
    int M, int N, int K,
    const float* __restrict__ bias, int biasZ,
    const float* __restrict__ res, int resZ, int ldres,
    const float* __restrict__ wvec)
{
    int z = blockIdx.z;
    A += (long long)z * aZ;
    B += (long long)z * bZ;
    C += (long long)z * cZ;
    bias += (long long)z * biasZ;
    if (EPI == 1 || EPI == 4) res += (long long)z * resZ;

    __shared__ __align__(16) float As[16][132];
    __shared__ __align__(16) float Bs[16][68];

    const int tid = threadIdx.x;
    const int tx = tid & 15, ty = tid >> 4;
    const int bm = blockIdx.y * 128, bn = blockIdx.x * 64;

    const int lr = tid >> 2;            // 0..63
    const int lc = (tid & 3) * 4;       // 0,4,8,12

    float acc[8][4];
    #pragma unroll
    for (int i = 0; i < 8; i++)
        #pragma unroll
        for (int j = 0; j < 4; j++) acc[i][j] = 0.f;

    for (int k0 = 0; k0 < K; k0 += 16) {
        float4 a0 = *(const float4*)&A[(long long)(bm + lr)      * lda + k0 + lc];
        float4 a1 = *(const float4*)&A[(long long)(bm + 64 + lr) * lda + k0 + lc];
        float4 b0 = *(const float4*)&B[(long long)(bn + lr)      * ldb + k0 + lc];
        if (k0) __syncthreads();
        As[lc+0][lr] = a0.x; As[lc+1][lr] = a0.y; As[lc+2][lr] = a0.z; As[lc+3][lr] = a0.w;
        As[lc+0][64+lr] = a1.x; As[lc+1][64+lr] = a1.y; As[lc+2][64+lr] = a1.z; As[lc+3][64+lr] = a1.w;
        Bs[lc+0][lr] = b0.x; Bs[lc+1][lr] = b0.y; Bs[lc+2][lr] = b0.z; Bs[lc+3][lr] = b0.w;
        __syncthreads();
        #pragma unroll
        for (int kk = 0; kk < 16; kk++) {
            float4 af0 = *(const float4*)&As[kk][ty * 8];
            float4 af1 = *(const float4*)&As[kk][ty * 8 + 4];
            float4 bf  = *(const float4*)&Bs[kk][tx * 4];
            float ar[8] = {af0.x, af0.y, af0.z, af0.w, af1.x, af1.y, af1.z, af1.w};
            float br[4] = {bf.x, bf.y, bf.z, bf.w};
            #pragma unroll
            for (int i = 0; i < 8; i++)
                #pragma unroll
                for (int j = 0; j < 4; j++)
                    acc[i][j] += ar[i] * br[j];
        }
    }

    const int row0 = bm + ty * 8;
    const int col0 = bn + tx * 4;
    #pragma unroll
    for (int i = 0; i < 8; i++) {
        long long r = row0 + i;
        float wsc = (EPI == 4) ? wvec[r * PATHS + z] : 0.f;
        #pragma unroll
        for (int j = 0; j < 4; j++) {
            int n = col0 + j;
            float v = acc[i][j] + bias[n];
            if (EPI == 1) v += res[r * ldres + n];
            if (EPI == 2) v = fmaxf(v, 0.f);
            if (EPI == 3) v = gelu_tanh(v);
            if (EPI == 4) v = res[r * ldres + n] + v * wsc;
            C[r * ldc + n] = v;
        }
    }
}

// ---------------- flash attention: 64 q-rows per block, Dh=64 ----------------
__global__ __launch_bounds__(256) void attn_kernel(
    const float* __restrict__ qkv, float* __restrict__ ctx)
{
    const int qb = blockIdx.x;     // 0..15 (q tile)
    const int h  = blockIdx.y;     // head
    const int b  = blockIdx.z;     // batch
    const float* base = qkv + (long long)b * S_LEN * 3 * HDIM;

    __shared__ __align__(16) float Qs[64][64];   // [d][qr], pre-scaled
    __shared__ __align__(16) float KP[64][64];   // K as [d][kc], then P as [kc][qr]
    __shared__ __align__(16) float Vs[64][64];   // [kv][d]

    const int tid = threadIdx.x;
    const int tx = tid & 15, ty = tid >> 4;

    // load Q (scaled by 1/sqrt(64)=0.125), transposed
    for (int i = tid; i < 64 * 16; i += 256) {
        int qr = i >> 4, d4 = (i & 15) * 4;
        float4 v = *(const float4*)&base[(long long)(qb * 64 + qr) * (3 * HDIM) + h * DHEAD + d4];
        Qs[d4+0][qr] = v.x * 0.125f; Qs[d4+1][qr] = v.y * 0.125f;
        Qs[d4+2][qr] = v.z * 0.125f; Qs[d4+3][qr] = v.w * 0.125f;
    }

    float m[4], l[4], o[4][4];
    #pragma unroll
    for (int i = 0; i < 4; i++) {
        m[i] = -1e30f; l[i] = 0.f;
        #pragma unroll
        for (int j = 0; j < 4; j++) o[i][j] = 0.f;
    }

    for (int kb = 0; kb <= qb; kb++) {
        __syncthreads();   // previous iteration's reads of KP/Vs are done
        for (int i = tid; i < 64 * 16; i += 256) {
            int kc = i >> 4, d4 = (i & 15) * 4;
            long long rowoff = (long long)(kb * 64 + kc) * (3 * HDIM) + h * DHEAD + d4;
            float4 kv = *(const float4*)&base[rowoff + HDIM];
            KP[d4+0][kc] = kv.x; KP[d4+1][kc] = kv.y; KP[d4+2][kc] = kv.z; KP[d4+3][kc] = kv.w;
            float4 vv = *(const float4*)&base[rowoff + 2 * HDIM];
            *(float4*)&Vs[kc][d4] = vv;
        }
        __syncthreads();

        // S = Q K^T
        float s[4][4];
        #pragma unroll
        for (int i = 0; i < 4; i++)
            #pragma unroll
            for (int j = 0; j < 4; j++) s[i][j] = 0.f;
        #pragma unroll 16
        for (int kk = 0; kk < 64; kk++) {
            float4 aq = *(const float4*)&Qs[kk][ty * 4];
            float4 bk = *(const float4*)&KP[kk][tx * 4];
            float ar[4] = {aq.x, aq.y, aq.z, aq.w};
            float br[4] = {bk.x, bk.y, bk.z, bk.w};
            #pragma unroll
            for (int i = 0; i < 4; i++)
                #pragma unroll
                for (int j = 0; j < 4; j++)
                    s[i][j] += ar[i] * br[j];
        }

        // causal mask on diagonal tile
        if (kb == qb) {
            #pragma unroll
            for (int i = 0; i < 4; i++) {
                int qg = ty * 4 + i;
                #pragma unroll
                for (int j = 0; j < 4; j++)
                    if (tx * 4 + j > qg) s[i][j] = -1e9f;
            }
        }

        // online softmax: per-row stats shared by the 16 tx-lanes of each ty group
        #pragma unroll
        for (int i = 0; i < 4; i++) {
            float rm = fmaxf(fmaxf(s[i][0], s[i][1]), fmaxf(s[i][2], s[i][3]));
            #pragma unroll
            for (int off = 1; off < 16; off <<= 1)
                rm = fmaxf(rm, __shfl_xor_sync(0xffffffffu, rm, off, 16));
            float mnew = fmaxf(m[i], rm);
            float scale = __expf(m[i] - mnew);
            m[i] = mnew;
            float rsum = 0.f;
            #pragma unroll
            for (int j = 0; j < 4; j++) {
                float p = __expf(s[i][j] - mnew);
                s[i][j] = p; rsum += p;
            }
            #pragma unroll
            for (int off = 1; off < 16; off <<= 1)
                rsum += __shfl_xor_sync(0xffffffffu, rsum, off, 16);
            l[i] = l[i] * scale + rsum;
            #pragma unroll
            for (int j = 0; j < 4; j++) o[i][j] *= scale;
        }

        __syncthreads();   // everyone finished reading KP (K data)
        #pragma unroll
        for (int i = 0; i < 4; i++)
            #pragma unroll
            for (int j = 0; j < 4; j++)
                KP[tx * 4 + j][ty * 4 + i] = s[i][j];
        __syncthreads();

        // O += P V
        #pragma unroll 16
        for (int kk = 0; kk < 64; kk++) {
            float4 ap = *(const float4*)&KP[kk][ty * 4];
            float4 bv = *(const float4*)&Vs[kk][tx * 4];
            float ar[4] = {ap.x, ap.y, ap.z, ap.w};
            float br[4] = {bv.x, bv.y, bv.z, bv.w};
            #pragma unroll
            for (int i = 0; i < 4; i++)
                #pragma unroll
                for (int j = 0; j < 4; j++)
                    o[i][j] += ar[i] * br[j];
        }
    }

    #pragma unroll
    for (int i = 0; i < 4; i++) {
        float inv = 1.0f / l[i];
        long long t = (long long)b * S_LEN + qb * 64 + ty * 4 + i;
        #pragma unroll
        for (int j = 0; j < 4; j++)
            ctx[t * HDIM + h * DHEAD + tx * 4 + j] = o[i][j] * inv;
    }
}

// ---------------- router: GEMV(16x256) + softmax + top-4 + renorm ------------
__global__ __launch_bounds__(128) void router_kernel(
    const float* __restrict__ r1, const float* __restrict__ Wr2,
    const float* __restrict__ br2, float* __restrict__ wout)
{
    int t = blockIdx.x;
    int tid = threadIdx.x;
    int p = tid >> 3, lane8 = tid & 7;

    const float4* a4 = (const float4*)(r1 + (long long)t * 256);
    const float4* w4 = (const float4*)(Wr2 + (long long)p * 256);
    float s = 0.f;
    #pragma unroll
    for (int j = 0; j < 8; j++) {
        float4 av = a4[lane8 * 8 + j];
        float4 wv = w4[lane8 * 8 + j];
        s += av.x * wv.x + av.y * wv.y + av.z * wv.z + av.w * wv.w;
    }
    #pragma unroll
    for (int o = 1; o < 8; o <<= 1) s += __shfl_xor_sync(0xffffffffu, s, o, 8);

    __shared__ float rv[16];
    if (lane8 == 0) rv[p] = s + br2[p];
    __syncthreads();

    if (tid == 0) {
        float pr[16];
        float vmax = rv[0];
        #pragma unroll
        for (int i = 1; i < 16; i++) vmax = fmaxf(vmax, rv[i]);
        float sum = 0.f;
        #pragma unroll
        for (int i = 0; i < 16; i++) { pr[i] = __expf(rv[i] - vmax); sum += pr[i]; }
        float inv = 1.0f / sum;
        #pragma unroll
        for (int i = 0; i < 16; i++) pr[i] *= inv;

        bool sel[16];
        #pragma unroll
        for (int i = 0; i < 16; i++) sel[i] = false;
        float ssum = 0.f;
        for (int k = 0; k < 4; k++) {
            int best = 0; float bv = -1.0f;
            for (int i = 0; i < 16; i++)
                if (!sel[i] && pr[i] > bv) { bv = pr[i]; best = i; }
            sel[best] = true; ssum += bv;
        }
        float dinv = 1.0f / (ssum + 1e-8f);
        for (int i = 0; i < 16; i++)
            wout[(long long)t * 16 + i] = sel[i] ? pr[i] * dinv : 0.f;
    }
}

// ---------------- launch ----------------
extern "C" void kernel_launch(void* const* d_in, const int* in_sizes, int n_in,
                              void* d_out, int out_size)
{
    const float* hidden = (const float*)d_in[0];
    const float* ln1w   = (const float*)d_in[1];
    const float* ln1b   = (const float*)d_in[2];
    const float* Wqkv   = (const float*)d_in[3];
    const float* bqkv   = (const float*)d_in[4];
    const float* Wo     = (const float*)d_in[5];
    const float* bo     = (const float*)d_in[6];
    const float* ln2w   = (const float*)d_in[7];
    const float* ln2b   = (const float*)d_in[8];
    const float* Wr1    = (const float*)d_in[9];
    const float* br1    = (const float*)d_in[10];
    const float* Wr2    = (const float*)d_in[11];
    const float* br2    = (const float*)d_in[12];
    const float* W1     = (const float*)d_in[13];
    const float* b1     = (const float*)d_in[14];
    const float* W2     = (const float*)d_in[15];
    const float* b2     = (const float*)d_in[16];
    float* out = (float*)d_out;

    float *x, *qkv, *ctx, *h, *x2, *r1, *wv, *inter;
    cudaGetSymbolAddress((void**)&x,     g_x_);
    cudaGetSymbolAddress((void**)&qkv,   g_qkv_);
    cudaGetSymbolAddress((void**)&ctx,   g_ctx_);
    cudaGetSymbolAddress((void**)&h,     g_h_);
    cudaGetSymbolAddress((void**)&x2,    g_x2_);
    cudaGetSymbolAddress((void**)&r1,    g_r1_);
    cudaGetSymbolAddress((void**)&wv,    g_w_);
    cudaGetSymbolAddress((void**)&inter, g_int_);

    // 1) LN1
    ln_kernel<<<NTOK, 256>>>(hidden, ln1w, ln1b, x);
    // 2) QKV = x @ Wqkv^T + bqkv            [4096 x 3072]
    sgemm_kernel<0><<<dim3(3072/64, NTOK/128, 1), 256>>>(
        x, HDIM, 0, Wqkv, HDIM, 0, qkv, 3*HDIM, 0, NTOK, 3*HDIM, HDIM,
        bqkv, 0, nullptr, 0, 0, nullptr);
    // 3) causal attention -> ctx
    attn_kernel<<<dim3(S_LEN/64, NHEADS, 4), 256>>>(qkv, ctx);
    // 4) h = hidden + ctx @ Wo^T + bo
    sgemm_kernel<1><<<dim3(HDIM/64, NTOK/128, 1), 256>>>(
        ctx, HDIM, 0, Wo, HDIM, 0, h, HDIM, 0, NTOK, HDIM, HDIM,
        bo, 0, hidden, 0, HDIM, nullptr);
    // 5) LN2
    ln_kernel<<<NTOK, 256>>>(h, ln2w, ln2b, x2);
    // 6) r1 = relu(x2 @ Wr1^T + br1)        [4096 x 256]
    sgemm_kernel<2><<<dim3(256/64, NTOK/128, 1), 256>>>(
        x2, HDIM, 0, Wr1, HDIM, 0, r1, 256, 0, NTOK, 256, HDIM,
        br1, 0, nullptr, 0, 0, nullptr);
    // 7) router logits + softmax + top-4 + renorm -> w [4096 x 16]
    router_kernel<<<NTOK, 128>>>(r1, Wr2, br2, wv);
    // 8) inter_p = gelu(x2_p @ W1b_p^T + b1_p)   (z = pathway)
    sgemm_kernel<3><<<dim3(256/64, NTOK/128, PATHS), 256>>>(
        x2, HDIM, 64, W1, HDIM, (long long)256*HDIM + 64,
        inter, 256, (long long)NTOK*256, NTOK, 256, 64,
        b1, 256, nullptr, 0, 0, nullptr);
    // 9) out = h + (inter_p @ W2b_p^T + b2_p) * w[:,p]   (z = pathway)
    sgemm_kernel<4><<<dim3(1, NTOK/128, PATHS), 256>>>(
        inter, 256, (long long)NTOK*256, W2, 4096, (long long)64*4096 + 256,
        out, HDIM, 64, NTOK, 64, 256,
        b2, 64, h, 64, HDIM, wv);
}

// round 6
// speedup vs baseline: 1.3472x; 1.3472x over previous
#include <cuda_runtime.h>
#include <math.h>
#include <stdint.h>

#define S_LEN  1024
#define HDIM   1024
#define NTOK   4096            // B*S
#define NHEADS 16
#define DHEAD  64
#define PATHS  16

// ---------------- scratch (static __device__, no allocation) ----------------
__device__ float4 g_x_   [NTOK*HDIM/4];        // ln1 out
__device__ float4 g_qkv_ [NTOK*3*HDIM/4];      // qkv
__device__ float4 g_ctx_ [NTOK*HDIM/4];        // attention context
__device__ float4 g_h_   [NTOK*HDIM/4];        // residual-1 out
__device__ float4 g_x2_  [NTOK*HDIM/4];        // ln2 out
__device__ float4 g_r1_  [NTOK*256/4];         // router hidden
__device__ float4 g_w_   [NTOK*PATHS/4];       // pathway weights
__device__ float4 g_int_ [(long long)PATHS*NTOK*256/4]; // pathway intermediates

// ---------------- LayerNorm (one block per row of 1024) ----------------
__global__ __launch_bounds__(256) void ln_kernel(
    const float* __restrict__ x, const float* __restrict__ gamma,
    const float* __restrict__ beta, float* __restrict__ y)
{
    long long row = blockIdx.x;
    const float* xr = x + row * HDIM;
    float* yr = y + row * HDIM;
    int tid = threadIdx.x;

    float4 v = *(const float4*)&xr[tid * 4];
    float s  = v.x + v.y + v.z + v.w;
    float ss = v.x*v.x + v.y*v.y + v.z*v.z + v.w*v.w;
    #pragma unroll
    for (int o = 16; o; o >>= 1) {
        s  += __shfl_xor_sync(0xffffffffu, s,  o);
        ss += __shfl_xor_sync(0xffffffffu, ss, o);
    }
    __shared__ float rs[8], rss[8];
    int w = tid >> 5, ln = tid & 31;
    if (ln == 0) { rs[w] = s; rss[w] = ss; }
    __syncthreads();
    s = 0.f; ss = 0.f;
    #pragma unroll
    for (int i = 0; i < 8; i++) { s += rs[i]; ss += rss[i]; }

    float mean = s * (1.0f / HDIM);
    float var  = ss * (1.0f / HDIM) - mean * mean;
    float inv  = rsqrtf(var + 1e-5f);

    float4 g = *(const float4*)&gamma[tid * 4];
    float4 b = *(const float4*)&beta[tid * 4];
    float4 o;
    o.x = (v.x - mean) * inv * g.x + b.x;
    o.y = (v.y - mean) * inv * g.y + b.y;
    o.z = (v.z - mean) * inv * g.z + b.z;
    o.w = (v.w - mean) * inv * g.w + b.w;
    *(float4*)&yr[tid * 4] = o;
}

// ---------------- tf32 tensor-core GEMM: C[M,N] = A[M,K] @ B[N,K]^T ---------
// BM=128, BN=64, BK=16, 256 threads (8 warps), warp tile 32x32 via
// mma.sync.m16n8k8.row.col.f32.tf32.tf32.f32.
// EPI: 0=bias  1=bias+res  2=bias+relu  3=gelu(bias)  4=res + (acc+bias)*w[row,z]
__device__ __forceinline__ float gelu_tanh(float x) {
    float t = tanhf(0.7978845608028654f * (x + 0.044715f * x * x * x));
    return 0.5f * x * (1.0f + t);
}

__device__ __forceinline__ uint32_t f2tf32(float x) {
    uint32_t r;
    asm("cvt.rna.tf32.f32 %0, %1;" : "=r"(r) : "f"(x));
    return r;
}

__device__ __forceinline__ void mma_tf32(float c[4], const uint32_t a[4], const uint32_t b[2]) {
    asm volatile(
        "mma.sync.aligned.m16n8k8.row.col.f32.tf32.tf32.f32 "
        "{%0,%1,%2,%3}, {%4,%5,%6,%7}, {%8,%9}, {%0,%1,%2,%3};\n"
        : "+f"(c[0]), "+f"(c[1]), "+f"(c[2]), "+f"(c[3])
        : "r"(a[0]), "r"(a[1]), "r"(a[2]), "r"(a[3]), "r"(b[0]), "r"(b[1]));
}

template<int EPI>
__global__ __launch_bounds__(256) void tgemm_kernel(
    const float* __restrict__ A, int lda, long long aZ,
    const float* __restrict__ B, int ldb, long long bZ,
    float* __restrict__ C, int ldc, long long cZ,
    int K,
    const float* __restrict__ bias, int biasZ,
    const float* __restrict__ res, int resZ, int ldres,
    const float* __restrict__ wvec)
{
    const int z = blockIdx.z;
    A += (long long)z * aZ;
    B += (long long)z * bZ;
    C += (long long)z * cZ;
    bias += (long long)z * biasZ;
    if (EPI == 1 || EPI == 4) res += (long long)z * resZ;

    // padded so fragment loads (bank = t*8+g) are conflict-free
    __shared__ uint32_t As[16][136];
    __shared__ uint32_t Bs[16][72];

    const int tid  = threadIdx.x;
    const int warp = tid >> 5;
    const int lane = tid & 31;
    const int g = lane >> 2;       // groupID (row within fragment)
    const int t = lane & 3;        // threadID_in_group
    const int wm = (warp & 3) * 32;    // warp m-offset in tile
    const int wn = (warp >> 2) * 32;   // warp n-offset in tile
    const int bm = blockIdx.y * 128, bn = blockIdx.x * 64;

    const int lr  = tid >> 2;          // 0..63
    const int lc4 = (tid & 3) * 4;     // 0,4,8,12

    float acc[2][4][4];
    #pragma unroll
    for (int i = 0; i < 2; i++)
        #pragma unroll
        for (int j = 0; j < 4; j++)
            #pragma unroll
            for (int q = 0; q < 4; q++) acc[i][j][q] = 0.f;

    for (int k0 = 0; k0 < K; k0 += 16) {
        float4 a0 = *(const float4*)&A[(long long)(bm + lr)      * lda + k0 + lc4];
        float4 a1 = *(const float4*)&A[(long long)(bm + 64 + lr) * lda + k0 + lc4];
        float4 b0 = *(const float4*)&B[(long long)(bn + lr)      * ldb + k0 + lc4];
        if (k0) __syncthreads();
        As[lc4+0][lr]    = f2tf32(a0.x); As[lc4+1][lr]    = f2tf32(a0.y);
        As[lc4+2][lr]    = f2tf32(a0.z); As[lc4+3][lr]    = f2tf32(a0.w);
        As[lc4+0][64+lr] = f2tf32(a1.x); As[lc4+1][64+lr] = f2tf32(a1.y);
        As[lc4+2][64+lr] = f2tf32(a1.z); As[lc4+3][64+lr] = f2tf32(a1.w);
        Bs[lc4+0][lr]    = f2tf32(b0.x); Bs[lc4+1][lr]    = f2tf32(b0.y);
        Bs[lc4+2][lr]    = f2tf32(b0.z); Bs[lc4+3][lr]    = f2tf32(b0.w);
        __syncthreads();

        #pragma unroll
        for (int ks = 0; ks < 16; ks += 8) {
            uint32_t af[2][4], bf[4][2];
            #pragma unroll
            for (int i = 0; i < 2; i++) {
                af[i][0] = As[ks + t    ][wm + 16*i + g];
                af[i][1] = As[ks + t    ][wm + 16*i + g + 8];
                af[i][2] = As[ks + t + 4][wm + 16*i + g];
                af[i][3] = As[ks + t + 4][wm + 16*i + g + 8];
            }
            #pragma unroll
            for (int j = 0; j < 4; j++) {
                bf[j][0] = Bs[ks + t    ][wn + 8*j + g];
                bf[j][1] = Bs[ks + t + 4][wn + 8*j + g];
            }
            #pragma unroll
            for (int i = 0; i < 2; i++)
                #pragma unroll
                for (int j = 0; j < 4; j++)
                    mma_tf32(acc[i][j], af[i], bf[j]);
        }
    }

    // epilogue: thread holds rows (bm+wm+16i+g) and (+8), cols (bn+wn+8j+2t, +1)
    #pragma unroll
    for (int i = 0; i < 2; i++) {
        const long long r0 = bm + wm + 16*i + g;
        const long long r1 = r0 + 8;
        float w0 = 0.f, w1 = 0.f;
        if (EPI == 4) { w0 = wvec[r0 * PATHS + z]; w1 = wvec[r1 * PATHS + z]; }
        #pragma unroll
        for (int j = 0; j < 4; j++) {
            const int col = bn + wn + 8*j + 2*t;
            const float bx = bias[col], by = bias[col + 1];
            float v0 = acc[i][j][0] + bx, v1 = acc[i][j][1] + by;   // row r0
            float v2 = acc[i][j][2] + bx, v3 = acc[i][j][3] + by;   // row r1
            if (EPI == 1) {
                float2 q0 = *(const float2*)&res[r0 * ldres + col];
                float2 q1 = *(const float2*)&res[r1 * ldres + col];
                v0 += q0.x; v1 += q0.y; v2 += q1.x; v3 += q1.y;
            }
            if (EPI == 2) { v0 = fmaxf(v0,0.f); v1 = fmaxf(v1,0.f); v2 = fmaxf(v2,0.f); v3 = fmaxf(v3,0.f); }
            if (EPI == 3) { v0 = gelu_tanh(v0); v1 = gelu_tanh(v1); v2 = gelu_tanh(v2); v3 = gelu_tanh(v3); }
            if (EPI == 4) {
                float2 q0 = *(const float2*)&res[r0 * ldres + col];
                float2 q1 = *(const float2*)&res[r1 * ldres + col];
                v0 = q0.x + v0 * w0; v1 = q0.y + v1 * w0;
                v2 = q1.x + v2 * w1; v3 = q1.y + v3 * w1;
            }
            *(float2*)&C[r0 * ldc + col] = make_float2(v0, v1);
            *(float2*)&C[r1 * ldc + col] = make_float2(v2, v3);
        }
    }
}

// ---------------- flash attention: 64 q-rows per block, Dh=64 ----------------
__global__ __launch_bounds__(256) void attn_kernel(
    const float* __restrict__ qkv, float* __restrict__ ctx)
{
    const int qb = blockIdx.x;     // 0..15 (q tile)
    const int h  = blockIdx.y;     // head
    const int b  = blockIdx.z;     // batch
    const float* base = qkv + (long long)b * S_LEN * 3 * HDIM;

    __shared__ __align__(16) float Qs[64][64];   // [d][qr], pre-scaled
    __shared__ __align__(16) float KP[64][64];   // K as [d][kc], then P as [kc][qr]
    __shared__ __align__(16) float Vs[64][64];   // [kv][d]

    const int tid = threadIdx.x;
    const int tx = tid & 15, ty = tid >> 4;

    // load Q (scaled by 1/sqrt(64)=0.125), transposed
    for (int i = tid; i < 64 * 16; i += 256) {
        int qr = i >> 4, d4 = (i & 15) * 4;
        float4 v = *(const float4*)&base[(long long)(qb * 64 + qr) * (3 * HDIM) + h * DHEAD + d4];
        Qs[d4+0][qr] = v.x * 0.125f; Qs[d4+1][qr] = v.y * 0.125f;
        Qs[d4+2][qr] = v.z * 0.125f; Qs[d4+3][qr] = v.w * 0.125f;
    }

    float m[4], l[4], o[4][4];
    #pragma unroll
    for (int i = 0; i < 4; i++) {
        m[i] = -1e30f; l[i] = 0.f;
        #pragma unroll
        for (int j = 0; j < 4; j++) o[i][j] = 0.f;
    }

    for (int kb = 0; kb <= qb; kb++) {
        __syncthreads();   // previous iteration's reads of KP/Vs are done
        for (int i = tid; i < 64 * 16; i += 256) {
            int kc = i >> 4, d4 = (i & 15) * 4;
            long long rowoff = (long long)(kb * 64 + kc) * (3 * HDIM) + h * DHEAD + d4;
            float4 kv = *(const float4*)&base[rowoff + HDIM];
            KP[d4+0][kc] = kv.x; KP[d4+1][kc] = kv.y; KP[d4+2][kc] = kv.z; KP[d4+3][kc] = kv.w;
            float4 vv = *(const float4*)&base[rowoff + 2 * HDIM];
            *(float4*)&Vs[kc][d4] = vv;
        }
        __syncthreads();

        // S = Q K^T
        float s[4][4];
        #pragma unroll
        for (int i = 0; i < 4; i++)
            #pragma unroll
            for (int j = 0; j < 4; j++) s[i][j] = 0.f;
        #pragma unroll 16
        for (int kk = 0; kk < 64; kk++) {
            float4 aq = *(const float4*)&Qs[kk][ty * 4];
            float4 bk = *(const float4*)&KP[kk][tx * 4];
            float ar[4] = {aq.x, aq.y, aq.z, aq.w};
            float br[4] = {bk.x, bk.y, bk.z, bk.w};
            #pragma unroll
            for (int i = 0; i < 4; i++)
                #pragma unroll
                for (int j = 0; j < 4; j++)
                    s[i][j] += ar[i] * br[j];
        }

        // causal mask on diagonal tile
        if (kb == qb) {
            #pragma unroll
            for (int i = 0; i < 4; i++) {
                int qg = ty * 4 + i;
                #pragma unroll
                for (int j = 0; j < 4; j++)
                    if (tx * 4 + j > qg) s[i][j] = -1e9f;
            }
        }

        // online softmax: per-row stats shared by the 16 tx-lanes of each ty group
        #pragma unroll
        for (int i = 0; i < 4; i++) {
            float rm = fmaxf(fmaxf(s[i][0], s[i][1]), fmaxf(s[i][2], s[i][3]));
            #pragma unroll
            for (int off = 1; off < 16; off <<= 1)
                rm = fmaxf(rm, __shfl_xor_sync(0xffffffffu, rm, off, 16));
            float mnew = fmaxf(m[i], rm);
            float scale = __expf(m[i] - mnew);
            m[i] = mnew;
            float rsum = 0.f;
            #pragma unroll
            for (int j = 0; j < 4; j++) {
                float p = __expf(s[i][j] - mnew);
                s[i][j] = p; rsum += p;
            }
            #pragma unroll
            for (int off = 1; off < 16; off <<= 1)
                rsum += __shfl_xor_sync(0xffffffffu, rsum, off, 16);
            l[i] = l[i] * scale + rsum;
            #pragma unroll
            for (int j = 0; j < 4; j++) o[i][j] *= scale;
        }

        __syncthreads();   // everyone finished reading KP (K data)
        #pragma unroll
        for (int i = 0; i < 4; i++)
            #pragma unroll
            for (int j = 0; j < 4; j++)
                KP[tx * 4 + j][ty * 4 + i] = s[i][j];
        __syncthreads();

        // O += P V
        #pragma unroll 16
        for (int kk = 0; kk < 64; kk++) {
            float4 ap = *(const float4*)&KP[kk][ty * 4];
            float4 bv = *(const float4*)&Vs[kk][tx * 4];
            float ar[4] = {ap.x, ap.y, ap.z, ap.w};
            float br[4] = {bv.x, bv.y, bv.z, bv.w};
            #pragma unroll
            for (int i = 0; i < 4; i++)
                #pragma unroll
                for (int j = 0; j < 4; j++)
                    o[i][j] += ar[i] * br[j];
        }
    }

    #pragma unroll
    for (int i = 0; i < 4; i++) {
        float inv = 1.0f / l[i];
        long long t = (long long)b * S_LEN + qb * 64 + ty * 4 + i;
        #pragma unroll
        for (int j = 0; j < 4; j++)
            ctx[t * HDIM + h * DHEAD + tx * 4 + j] = o[i][j] * inv;
    }
}

// ---------------- router: GEMV(16x256) + softmax + top-4 + renorm ------------
__global__ __launch_bounds__(128) void router_kernel(
    const float* __restrict__ r1, const float* __restrict__ Wr2,
    const float* __restrict__ br2, float* __restrict__ wout)
{
    int t = blockIdx.x;
    int tid = threadIdx.x;
    int p = tid >> 3, lane8 = tid & 7;

    const float4* a4 = (const float4*)(r1 + (long long)t * 256);
    const float4* w4 = (const float4*)(Wr2 + (long long)p * 256);
    float s = 0.f;
    #pragma unroll
    for (int j = 0; j < 8; j++) {
        float4 av = a4[lane8 * 8 + j];
        float4 wv = w4[lane8 * 8 + j];
        s += av.x * wv.x + av.y * wv.y + av.z * wv.z + av.w * wv.w;
    }
    #pragma unroll
    for (int o = 1; o < 8; o <<= 1) s += __shfl_xor_sync(0xffffffffu, s, o, 8);

    __shared__ float rv[16];
    if (lane8 == 0) rv[p] = s + br2[p];
    __syncthreads();

    if (tid == 0) {
        float pr[16];
        float vmax = rv[0];
        #pragma unroll
        for (int i = 1; i < 16; i++) vmax = fmaxf(vmax, rv[i]);
        float sum = 0.f;
        #pragma unroll
        for (int i = 0; i < 16; i++) { pr[i] = __expf(rv[i] - vmax); sum += pr[i]; }
        float inv = 1.0f / sum;
        #pragma unroll
        for (int i = 0; i < 16; i++) pr[i] *= inv;

        bool sel[16];
        #pragma unroll
        for (int i = 0; i < 16; i++) sel[i] = false;
        float ssum = 0.f;
        for (int k = 0; k < 4; k++) {
            int best = 0; float bv = -1.0f;
            for (int i = 0; i < 16; i++)
                if (!sel[i] && pr[i] > bv) { bv = pr[i]; best = i; }
            sel[best] = true; ssum += bv;
        }
        float dinv = 1.0f / (ssum + 1e-8f);
        for (int i = 0; i < 16; i++)
            wout[(long long)t * 16 + i] = sel[i] ? pr[i] * dinv : 0.f;
    }
}

// ---------------- launch ----------------
extern "C" void kernel_launch(void* const* d_in, const int* in_sizes, int n_in,
                              void* d_out, int out_size)
{
    const float* hidden = (const float*)d_in[0];
    const float* ln1w   = (const float*)d_in[1];
    const float* ln1b   = (const float*)d_in[2];
    const float* Wqkv   = (const float*)d_in[3];
    const float* bqkv   = (const float*)d_in[4];
    const float* Wo     = (const float*)d_in[5];
    const float* bo     = (const float*)d_in[6];
    const float* ln2w   = (const float*)d_in[7];
    const float* ln2b   = (const float*)d_in[8];
    const float* Wr1    = (const float*)d_in[9];
    const float* br1    = (const float*)d_in[10];
    const float* Wr2    = (const float*)d_in[11];
    const float* br2    = (const float*)d_in[12];
    const float* W1     = (const float*)d_in[13];
    const float* b1     = (const float*)d_in[14];
    const float* W2     = (const float*)d_in[15];
    const float* b2     = (const float*)d_in[16];
    float* out = (float*)d_out;

    float *x, *qkv, *ctx, *h, *x2, *r1, *wv, *inter;
    cudaGetSymbolAddress((void**)&x,     g_x_);
    cudaGetSymbolAddress((void**)&qkv,   g_qkv_);
    cudaGetSymbolAddress((void**)&ctx,   g_ctx_);
    cudaGetSymbolAddress((void**)&h,     g_h_);
    cudaGetSymbolAddress((void**)&x2,    g_x2_);
    cudaGetSymbolAddress((void**)&r1,    g_r1_);
    cudaGetSymbolAddress((void**)&wv,    g_w_);
    cudaGetSymbolAddress((void**)&inter, g_int_);

    // 1) LN1
    ln_kernel<<<NTOK, 256>>>(hidden, ln1w, ln1b, x);
    // 2) QKV = x @ Wqkv^T + bqkv            [4096 x 3072]
    tgemm_kernel<0><<<dim3(3072/64, NTOK/128, 1), 256>>>(
        x, HDIM, 0, Wqkv, HDIM, 0, qkv, 3*HDIM, 0, HDIM,
        bqkv, 0, nullptr, 0, 0, nullptr);
    // 3) causal attention -> ctx
    attn_kernel<<<dim3(S_LEN/64, NHEADS, 4), 256>>>(qkv, ctx);
    // 4) h = hidden + ctx @ Wo^T + bo
    tgemm_kernel<1><<<dim3(HDIM/64, NTOK/128, 1), 256>>>(
        ctx, HDIM, 0, Wo, HDIM, 0, h, HDIM, 0, HDIM,
        bo, 0, hidden, 0, HDIM, nullptr);
    // 5) LN2
    ln_kernel<<<NTOK, 256>>>(h, ln2w, ln2b, x2);
    // 6) r1 = relu(x2 @ Wr1^T + br1)        [4096 x 256]
    tgemm_kernel<2><<<dim3(256/64, NTOK/128, 1), 256>>>(
        x2, HDIM, 0, Wr1, HDIM, 0, r1, 256, 0, HDIM,
        br1, 0, nullptr, 0, 0, nullptr);
    // 7) router logits + softmax + top-4 + renorm -> w [4096 x 16]
    router_kernel<<<NTOK, 128>>>(r1, Wr2, br2, wv);
    // 8) inter_p = gelu(x2_p @ W1b_p^T + b1_p)   (z = pathway)
    tgemm_kernel<3><<<dim3(256/64, NTOK/128, PATHS), 256>>>(
        x2, HDIM, 64, W1, HDIM, (long long)256*HDIM + 64,
        inter, 256, (long long)NTOK*256, 64,
        b1, 256, nullptr, 0, 0, nullptr);
    // 9) out = h + (inter_p @ W2b_p^T + b2_p) * w[:,p]   (z = pathway)
    tgemm_kernel<4><<<dim3(1, NTOK/128, PATHS), 256>>>(
        inter, 256, (long long)NTOK*256, W2, 4096, (long long)64*4096 + 256,
        out, HDIM, 64, 256,
        b2, 64, h, 64, HDIM, wv);
}